// round 3
// baseline (speedup 1.0000x reference)
#include <cuda_runtime.h>
#include <cuda_bf16.h>
#include <cstdint>

#define Bn 256
#define Sn 2048
#define Tn 32
#define FULLMASK 0xffffffffu
#define LOG32F 3.4657359027997265f

// Scratch (device globals are the sanctioned scratch mechanism)
__device__ unsigned char g_hist[(size_t)Bn * (Sn - 1) * Tn];  // backpointers, 16.8 MB
__device__ float g_den[Bn];
__device__ float g_num[Bn];
__device__ int   g_last[Bn];

// ---- packed f32x2 helpers (Blackwell) -------------------------------------
__device__ __forceinline__ float2 fadd2(float2 a, float2 b) {
    union { float2 f; unsigned long long u; } A, B, R;
    A.f = a; B.f = b;
    asm("add.rn.f32x2 %0, %1, %2;" : "=l"(R.u) : "l"(A.u), "l"(B.u));
    return R.f;
}
__device__ __forceinline__ float2 ffma2(float2 a, float2 b, float2 c) {
    union { float2 f; unsigned long long u; } A, B, C, R;
    A.f = a; B.f = b; C.f = c;
    asm("fma.rn.f32x2 %0, %1, %2, %3;" : "=l"(R.u) : "l"(A.u), "l"(B.u), "l"(C.u));
    return R.f;
}

// ---------------------------------------------------------------------------
// Forward algorithm, linear domain with deferred renorm.
// ---------------------------------------------------------------------------
template<bool AM>
__device__ __forceinline__ void fwd_loop(const float* __restrict__ em, int j,
                                         float* __restrict__ bufw,
                                         const signed char* __restrict__ mk,
                                         const float* __restrict__ startv,
                                         const float* __restrict__ endv,
                                         const float* __restrict__ trans,
                                         int b)
{
    float2 tc2[16];
    #pragma unroll
    for (int k = 0; k < 16; ++k) {
        float2 p;
        p.x = __expf(trans[(2 * k + 0) * Tn + j]) * 0.03125f;
        p.y = __expf(trans[(2 * k + 1) * Tn + j]) * 0.03125f;
        tc2[k] = p;
    }

    float s  = __expf(startv[j] + em[j]);
    float Lr = 0.f;
    int   nm = 0;

    float raw_[4], ee_[4];
    #pragma unroll
    for (int p = 0; p < 4; ++p) ee_[p]  = __expf(em[(size_t)(1 + p) * Tn + j]);
    #pragma unroll
    for (int p = 0; p < 4; ++p) raw_[p] = em[(size_t)(5 + p) * Tn + j];

    for (int tb = 1; tb < Sn; tb += 4) {
        #pragma unroll
        for (int u = 0; u < 4; ++u) {
            const int t = tb + u;
            if (t >= Sn) break;
            const float ee = ee_[u];
            ee_[u] = __expf(raw_[u]);                       // for t+4
            const int t8 = t + 8;
            if (t8 < Sn) raw_[u] = em[(size_t)t8 * Tn + j]; // prefetch

            float* sb = bufw + (t & 1) * 32;
            sb[j] = s;
            __syncwarp();

            float2 a0 = {0.f, 0.f}, a1 = {0.f, 0.f}, a2 = {0.f, 0.f}, a3 = {0.f, 0.f};
            #pragma unroll
            for (int k = 0; k < 4; ++k) {
                const float4 qa = *(const float4*)(sb + 8 * k);
                const float4 qb = *(const float4*)(sb + 8 * k + 4);
                a0 = ffma2(make_float2(qa.x, qa.y), tc2[4 * k + 0], a0);
                a1 = ffma2(make_float2(qa.z, qa.w), tc2[4 * k + 1], a1);
                a2 = ffma2(make_float2(qb.x, qb.y), tc2[4 * k + 2], a2);
                a3 = ffma2(make_float2(qb.z, qb.w), tc2[4 * k + 3], a3);
            }
            const float2 a01 = fadd2(a0, a1);
            const float2 a23 = fadd2(a2, a3);
            const float2 aa  = fadd2(a01, a23);
            const float ns = (aa.x + aa.y) * ee;
            if (AM) {
                s = ns;
            } else {
                const int m_ = mk[t];
                s = m_ ? ns : s;
                nm += (m_ != 0);
            }

            if ((t & 15) == 15) {                           // amortized renorm
                const float r  = __shfl_sync(FULLMASK, s, 0);
                const float rr = __frcp_rn(r);
                s *= rr;
                Lr -= __logf(rr);
            }
        }
    }
    if (AM) nm = Sn - 1;
    float v = s * __expf(endv[j]);
    #pragma unroll
    for (int off = 16; off; off >>= 1)
        v += __shfl_xor_sync(FULLMASK, v, off);
    if (j == 0) g_den[b] = (float)nm * LOG32F + Lr + __logf(v);
}

// ---------------------------------------------------------------------------
// Viterbi: FMNMX value tree (bit-exact) + left-priority tournament argmax
// (identical to first-occurrence jnp.argmax).
// ---------------------------------------------------------------------------
template<bool AM>
__device__ __forceinline__ void vit_loop(const float* __restrict__ em, int j,
                                         float* __restrict__ bufw,
                                         const signed char* __restrict__ mk,
                                         const float* __restrict__ startv,
                                         const float* __restrict__ endv,
                                         const float* __restrict__ trans,
                                         int b)
{
    float2 tc2[16];
    #pragma unroll
    for (int k = 0; k < 16; ++k) {
        float2 p;
        p.x = trans[(2 * k + 0) * Tn + j];
        p.y = trans[(2 * k + 1) * Tn + j];
        tc2[k] = p;
    }

    float v = startv[j] + em[j];
    unsigned char* hb = g_hist + (size_t)b * (Sn - 1) * Tn;

    float emreg[4];
    #pragma unroll
    for (int p = 0; p < 4; ++p) emreg[p] = em[(size_t)(1 + p) * Tn + j];

    for (int tb = 1; tb < Sn; tb += 4) {
        #pragma unroll
        for (int u = 0; u < 4; ++u) {
            const int t = tb + u;
            if (t >= Sn) break;
            const float emt = emreg[u];
            const int tn = t + 4;
            if (tn < Sn) emreg[u] = em[(size_t)tn * Tn + j];

            float* vb = bufw + (t & 1) * 32;
            vb[j] = v;
            __syncwarp();

            // L1: 16 merged pairs (value + index)
            float tv[16]; int ti[16];
            #pragma unroll
            for (int k = 0; k < 8; ++k) {
                const float4 q = *(const float4*)(vb + 4 * k);
                const float2 p0 = fadd2(make_float2(q.x, q.y), tc2[2 * k + 0]);
                const float2 p1 = fadd2(make_float2(q.z, q.w), tc2[2 * k + 1]);
                const bool s0 = p0.y > p0.x;
                tv[2 * k + 0] = fmaxf(p0.x, p0.y);
                ti[2 * k + 0] = s0 ? (4 * k + 1) : (4 * k + 0);
                const bool s1 = p1.y > p1.x;
                tv[2 * k + 1] = fmaxf(p1.x, p1.y);
                ti[2 * k + 1] = s1 ? (4 * k + 3) : (4 * k + 2);
            }
            // L2..L5 (left wins ties -> first occurrence)
            float uv[8]; int ui[8];
            #pragma unroll
            for (int i = 0; i < 8; ++i) {
                const bool p = tv[2 * i + 1] > tv[2 * i];
                uv[i] = fmaxf(tv[2 * i], tv[2 * i + 1]);
                ui[i] = p ? ti[2 * i + 1] : ti[2 * i];
            }
            float wv[4]; int wi[4];
            #pragma unroll
            for (int i = 0; i < 4; ++i) {
                const bool p = uv[2 * i + 1] > uv[2 * i];
                wv[i] = fmaxf(uv[2 * i], uv[2 * i + 1]);
                wi[i] = p ? ui[2 * i + 1] : ui[2 * i];
            }
            const bool pa = wv[1] > wv[0];
            const float xv0 = fmaxf(wv[0], wv[1]);
            const int   xi0 = pa ? wi[1] : wi[0];
            const bool pb = wv[3] > wv[2];
            const float xv1 = fmaxf(wv[2], wv[3]);
            const int   xi1 = pb ? wi[3] : wi[2];
            const bool pc = xv1 > xv0;
            const float m  = fmaxf(xv0, xv1);
            const int   bi = pc ? xi1 : xi0;

            const float nv = m + emt;
            if (AM) {
                v = nv;
                hb[(size_t)(t - 1) * Tn + j] = (unsigned char)bi;
            } else {
                const int m_ = mk[t];
                const int bp = m_ ? bi : j;
                v = m_ ? nv : v;
                hb[(size_t)(t - 1) * Tn + j] = (unsigned char)bp;
            }
        }
    }
    // last_tag = argmax_j (v_j + end_j), lowest index on ties
    float bv = v + endv[j];
    int   bidx = j;
    #pragma unroll
    for (int off = 16; off; off >>= 1) {
        const float ov = __shfl_xor_sync(FULLMASK, bv, off);
        const int   oi = __shfl_xor_sync(FULLMASK, bidx, off);
        const bool take = (ov > bv) || (ov == bv && oi < bidx);
        bv   = take ? ov : bv;
        bidx = take ? oi : bidx;
    }
    if (j == 0) g_last[b] = bidx;
}

// ---------------------------------------------------------------------------
// Main kernel: 192 CTAs x 128 threads (4 warps = 4 batches per CTA).
//   blocks   0..63 : forward  (batches 4*(bid)    ..)
//   blocks  64..127: viterbi
//   blocks 128..191: numerator
// 4-warp CTAs spread warps across all 4 SMSPs (wid % 4).
// ---------------------------------------------------------------------------
__global__ __launch_bounds__(128)
void crf_main_kernel(const float* __restrict__ pred,
                     const int*   __restrict__ amask,
                     const int*   __restrict__ labels,
                     const float* __restrict__ startv,
                     const float* __restrict__ endv,
                     const float* __restrict__ trans)
{
    const int role = blockIdx.x >> 6;
    const int wib  = threadIdx.x >> 5;
    const int b    = ((blockIdx.x & 63) << 2) | wib;
    const int j    = threadIdx.x & 31;

    const float* em = pred + (size_t)b * Sn * Tn;

    __shared__ __align__(16) float buf[4][2][32];
    __shared__ signed char mkS[4][Sn];

    if (role == 2) {
        // ------- Numerator --------------------------------------------------
        const int* lab = labels + (size_t)b * Sn;
        const int* am  = amask  + (size_t)b * Sn;
        float sum = 0.f;
        int   msum = 0;
        for (int t = j; t < Sn; t += 32) {
            const int mt = am[t];
            msum += mt;
            const int tg = lab[t];
            if (t == 0) {
                sum += startv[tg] + em[tg];
            } else {
                const int tp = lab[t - 1];
                sum += (trans[tp * Tn + tg] + em[(size_t)t * Tn + tg]) * (float)mt;
            }
        }
        #pragma unroll
        for (int off = 16; off; off >>= 1) {
            sum  += __shfl_xor_sync(FULLMASK, sum, off);
            msum += __shfl_xor_sync(FULLMASK, msum, off);
        }
        if (j == 0) {
            const int se = msum - 1;
            const int lt = lab[se];
            g_num[b] = sum + endv[lt];
        }
        return;
    }

    // Load mask, detect all-ones (fast path valid for any input)
    const int* am = amask + (size_t)b * Sn;
    int okv = 1;
    for (int t = j; t < Sn; t += 32) {
        const int mv = am[t];
        mkS[wib][t] = (signed char)mv;
        okv &= (mv == 1);
    }
    const bool allones = __all_sync(FULLMASK, okv != 0);
    __syncwarp();

    float* bufw = &buf[wib][0][0];
    if (role == 0) {
        if (allones) fwd_loop<true >(em, j, bufw, mkS[wib], startv, endv, trans, b);
        else         fwd_loop<false>(em, j, bufw, mkS[wib], startv, endv, trans, b);
    } else {
        if (allones) vit_loop<true >(em, j, bufw, mkS[wib], startv, endv, trans, b);
        else         vit_loop<false>(em, j, bufw, mkS[wib], startv, endv, trans, b);
    }
}

// ---------------------------------------------------------------------------
// Backtrace: one warp per batch. Double-buffered chunk prefetch (lanes 1..31)
// overlaps lane 0's serial LDS pointer-chase; conversion/stores by all lanes.
// ---------------------------------------------------------------------------
__global__ __launch_bounds__(32)
void crf_backtrace_kernel(float* __restrict__ out)
{
    const int b = blockIdx.x;
    const int lane = threadIdx.x;
    __shared__ __align__(16) unsigned char rows[2][32 * Tn];
    __shared__ unsigned char stag[32];
    __shared__ int s_tag;

    const unsigned char* hb = g_hist + (size_t)b * (Sn - 1) * Tn;
    float* ob = out + (size_t)b * Sn;

    int r  = Sn - 2;
    int c0 = r - 31; if (c0 < 0) c0 = 0;
    {   // load first chunk (all lanes)
        const int n = r - c0 + 1;
        const uint32_t* src = (const uint32_t*)(hb + (size_t)c0 * Tn);
        uint32_t* dst = (uint32_t*)rows[0];
        for (int idx = lane; idx < n * 8; idx += 32) dst[idx] = src[idx];
    }
    if (lane == 0) {
        s_tag = g_last[b];
        ob[Sn - 1] = (float)s_tag;
    }
    __syncwarp();

    int cur = 0;
    while (r >= 0) {
        const int n  = r - c0 + 1;
        const int r2 = c0 - 1;
        int c02 = r2 - 31; if (c02 < 0) c02 = 0;

        if (r2 >= 0 && lane >= 1) {          // prefetch next chunk, lanes 1..31
            const int n2 = r2 - c02 + 1;
            const uint32_t* src = (const uint32_t*)(hb + (size_t)c02 * Tn);
            uint32_t* dst = (uint32_t*)rows[cur ^ 1];
            for (int idx = lane - 1; idx < n2 * 8; idx += 31) dst[idx] = src[idx];
        }
        if (lane == 0) {                     // serial pointer chase in SMEM
            int tag = s_tag;
            const unsigned char* R = rows[cur];
            for (int k = n - 1; k >= 0; --k) {
                tag = R[k * Tn + tag];
                stag[k] = (unsigned char)tag;
            }
            s_tag = tag;
        }
        __syncwarp();
        if (lane < n) ob[c0 + lane] = (float)stag[lane];
        cur ^= 1;
        r = r2;
        c0 = c02;
        __syncwarp();
    }
}

// ---------------------------------------------------------------------------
// Loss: -mean(num - den)
// ---------------------------------------------------------------------------
__global__ void crf_loss_kernel(float* __restrict__ out)
{
    __shared__ float red[Bn];
    const int t = threadIdx.x;
    red[t] = g_num[t] - g_den[t];
    __syncthreads();
    #pragma unroll
    for (int off = 128; off; off >>= 1) {
        if (t < off) red[t] += red[t + off];
        __syncthreads();
    }
    if (t == 0) out[(size_t)Bn * Sn] = -(red[0] / (float)Bn);
}

extern "C" void kernel_launch(void* const* d_in, const int* in_sizes, int n_in,
                              void* d_out, int out_size)
{
    const float* pred   = (const float*)d_in[0];
    const int*   amask  = (const int*)  d_in[1];
    const int*   labels = (const int*)  d_in[2];
    const float* startv = (const float*)d_in[3];
    const float* endv   = (const float*)d_in[4];
    const float* trans  = (const float*)d_in[5];
    float* out = (float*)d_out;

    crf_main_kernel<<<192, 128>>>(pred, amask, labels, startv, endv, trans);
    crf_backtrace_kernel<<<Bn, 32>>>(out);
    crf_loss_kernel<<<1, Bn>>>(out);
}

// round 4
// speedup vs baseline: 2.7199x; 2.7199x over previous
#include <cuda_runtime.h>
#include <cuda_bf16.h>
#include <cstdint>

#define Bn 256
#define Sn 2048
#define Tn 32
#define NCH 64
#define FULLMASK 0xffffffffu
#define LOG32F 3.4657359027997265f

// Scratch (device globals are the sanctioned scratch mechanism)
__device__ unsigned char g_hist[(size_t)Bn * (Sn - 1) * Tn];  // backpointers
__device__ unsigned char g_map[Bn][NCH][Tn];                  // chunk tag maps
__device__ unsigned char g_ent[Bn][NCH];                      // chunk entry tags
__device__ float g_den[Bn];
__device__ float g_num[Bn];
__device__ int   g_last[Bn];

// ---- packed f32x2 helpers (Blackwell) -------------------------------------
__device__ __forceinline__ float2 fadd2(float2 a, float2 b) {
    union { float2 f; unsigned long long u; } A, B, R;
    A.f = a; B.f = b;
    asm("add.rn.f32x2 %0, %1, %2;" : "=l"(R.u) : "l"(A.u), "l"(B.u));
    return R.f;
}
__device__ __forceinline__ float2 ffma2(float2 a, float2 b, float2 c) {
    union { float2 f; unsigned long long u; } A, B, C, R;
    A.f = a; B.f = b; C.f = c;
    asm("fma.rn.f32x2 %0, %1, %2, %3;" : "=l"(R.u) : "l"(A.u), "l"(B.u), "l"(C.u));
    return R.f;
}

// ---- cp.async helpers ------------------------------------------------------
__device__ __forceinline__ uint32_t smem_u32(const void* p) {
    return (uint32_t)__cvta_generic_to_shared(p);
}
__device__ __forceinline__ void cp4(uint32_t d, const void* s) {
    asm volatile("cp.async.ca.shared.global [%0], [%1], 4;" :: "r"(d), "l"(s));
}
#define CP_COMMIT() asm volatile("cp.async.commit_group;")
#define CP_WAIT10() asm volatile("cp.async.wait_group 10;")

// prefetch ring: 16 stages, issue 12 ahead, wait leaves <=10 pending
#define RD 12

// ---------------------------------------------------------------------------
// Forward algorithm, linear domain with deferred renorm. em via cp.async ring.
// ---------------------------------------------------------------------------
template<bool AM>
__device__ __forceinline__ void fwd_loop(const float* __restrict__ em, int j,
                                         float* __restrict__ bufw,
                                         float* __restrict__ ringw,
                                         const signed char* __restrict__ mk,
                                         const float* __restrict__ startv,
                                         const float* __restrict__ endv,
                                         const float* __restrict__ trans,
                                         int b)
{
    float2 tc2[16];
    #pragma unroll
    for (int k = 0; k < 16; ++k) {
        float2 p;
        p.x = __expf(trans[(2 * k + 0) * Tn + j]) * 0.03125f;
        p.y = __expf(trans[(2 * k + 1) * Tn + j]) * 0.03125f;
        tc2[k] = p;
    }

    const uint32_t rbase = smem_u32(ringw);
    #pragma unroll
    for (int p = 1; p <= RD; ++p) {
        cp4(rbase + (((p & 15) * 32 + j) << 2), em + (size_t)p * Tn + j);
        CP_COMMIT();
    }

    float s  = __expf(startv[j] + em[j]);
    float Lr = 0.f;
    int   nm = 0;

    #pragma unroll 4
    for (int t = 1; t < Sn; ++t) {
        CP_WAIT10();
        float* sb = bufw + (t & 1) * 32;
        sb[j] = s;
        __syncwarp();
        const float emv = ringw[(t & 15) * 32 + j];
        const float ee  = __expf(emv);

        float2 a0 = {0.f, 0.f}, a1 = {0.f, 0.f}, a2 = {0.f, 0.f}, a3 = {0.f, 0.f};
        #pragma unroll
        for (int k = 0; k < 4; ++k) {
            const float4 qa = *(const float4*)(sb + 8 * k);
            const float4 qb = *(const float4*)(sb + 8 * k + 4);
            a0 = ffma2(make_float2(qa.x, qa.y), tc2[4 * k + 0], a0);
            a1 = ffma2(make_float2(qa.z, qa.w), tc2[4 * k + 1], a1);
            a2 = ffma2(make_float2(qb.x, qb.y), tc2[4 * k + 2], a2);
            a3 = ffma2(make_float2(qb.z, qb.w), tc2[4 * k + 3], a3);
        }
        const float2 a01 = fadd2(a0, a1);
        const float2 a23 = fadd2(a2, a3);
        const float2 aa  = fadd2(a01, a23);
        const float ns = (aa.x + aa.y) * ee;
        if (AM) {
            s = ns;
        } else {
            const int m_ = mk[t];
            s = m_ ? ns : s;
            nm += (m_ != 0);
        }

        // refill ring (clamped tail keeps group accounting uniform)
        const int tf = t + RD;
        const int tc = tf < Sn - 1 ? tf : Sn - 1;
        cp4(rbase + ((((tf & 15) * 32) + j) << 2), em + (size_t)tc * Tn + j);
        CP_COMMIT();

        if ((t & 15) == 15) {                           // amortized renorm
            const float r  = __shfl_sync(FULLMASK, s, 0);
            const float rr = __frcp_rn(r);
            s *= rr;
            Lr -= __logf(rr);
        }
    }
    if (AM) nm = Sn - 1;
    float v = s * __expf(endv[j]);
    #pragma unroll
    for (int off = 16; off; off >>= 1)
        v += __shfl_xor_sync(FULLMASK, v, off);
    if (j == 0) g_den[b] = (float)nm * LOG32F + Lr + __logf(v);
}

// ---------------------------------------------------------------------------
// Viterbi: pair-max + FMNMX tree (bit-exact value), first-occurrence argmax
// via pair-equality scan + packed selection bitmask. em via cp.async ring.
// ---------------------------------------------------------------------------
template<bool AM>
__device__ __forceinline__ void vit_loop(const float* __restrict__ em, int j,
                                         float* __restrict__ bufw,
                                         float* __restrict__ ringw,
                                         const signed char* __restrict__ mk,
                                         const float* __restrict__ startv,
                                         const float* __restrict__ endv,
                                         const float* __restrict__ trans,
                                         int b)
{
    float2 tc2[16];
    #pragma unroll
    for (int k = 0; k < 16; ++k) {
        float2 p;
        p.x = trans[(2 * k + 0) * Tn + j];
        p.y = trans[(2 * k + 1) * Tn + j];
        tc2[k] = p;
    }

    const uint32_t rbase = smem_u32(ringw);
    #pragma unroll
    for (int p = 1; p <= RD; ++p) {
        cp4(rbase + (((p & 15) * 32 + j) << 2), em + (size_t)p * Tn + j);
        CP_COMMIT();
    }

    float v = startv[j] + em[j];
    unsigned char* hb = g_hist + (size_t)b * (Sn - 1) * Tn;

    #pragma unroll 4
    for (int t = 1; t < Sn; ++t) {
        CP_WAIT10();
        float* vb = bufw + (t & 1) * 32;
        vb[j] = v;
        __syncwarp();
        const float emt = ringw[(t & 15) * 32 + j];

        float tv[16];
        uint32_t selm = 0;
        #pragma unroll
        for (int k = 0; k < 8; ++k) {
            const float4 q = *(const float4*)(vb + 4 * k);
            const float2 pa = fadd2(make_float2(q.x, q.y), tc2[2 * k + 0]);
            const float2 pb = fadd2(make_float2(q.z, q.w), tc2[2 * k + 1]);
            tv[2 * k + 0] = fmaxf(pa.x, pa.y);
            selm |= (pa.y > pa.x ? 1u : 0u) << (2 * k + 0);
            tv[2 * k + 1] = fmaxf(pb.x, pb.y);
            selm |= (pb.y > pb.x ? 1u : 0u) << (2 * k + 1);
        }
        // value tree (order-independent, bit-exact)
        float u0 = fmaxf(tv[0], tv[1]),  u1 = fmaxf(tv[2], tv[3]);
        float u2 = fmaxf(tv[4], tv[5]),  u3 = fmaxf(tv[6], tv[7]);
        float u4 = fmaxf(tv[8], tv[9]),  u5 = fmaxf(tv[10], tv[11]);
        float u6 = fmaxf(tv[12], tv[13]), u7 = fmaxf(tv[14], tv[15]);
        float w0 = fmaxf(u0, u1), w1 = fmaxf(u2, u3);
        float w2 = fmaxf(u4, u5), w3 = fmaxf(u6, u7);
        const float m = fmaxf(fmaxf(w0, w1), fmaxf(w2, w3));

        // first pair index with pair-max == m (descending scan, off-chain)
        int p = 15;
        #pragma unroll
        for (int i = 14; i >= 0; --i)
            p = (tv[i] == m) ? i : p;
        const int bi = 2 * p + (int)((selm >> p) & 1u);

        const float nv = m + emt;
        if (AM) {
            v = nv;
            hb[(size_t)(t - 1) * Tn + j] = (unsigned char)bi;
        } else {
            const int m_ = mk[t];
            const int bp = m_ ? bi : j;
            v = m_ ? nv : v;
            hb[(size_t)(t - 1) * Tn + j] = (unsigned char)bp;
        }

        const int tf = t + RD;
        const int tcl = tf < Sn - 1 ? tf : Sn - 1;
        cp4(rbase + ((((tf & 15) * 32) + j) << 2), em + (size_t)tcl * Tn + j);
        CP_COMMIT();
    }
    // last_tag = argmax_j (v_j + end_j), lowest index on ties
    float bv = v + endv[j];
    int   bidx = j;
    #pragma unroll
    for (int off = 16; off; off >>= 1) {
        const float ov = __shfl_xor_sync(FULLMASK, bv, off);
        const int   oi = __shfl_xor_sync(FULLMASK, bidx, off);
        const bool take = (ov > bv) || (ov == bv && oi < bidx);
        bv   = take ? ov : bv;
        bidx = take ? oi : bidx;
    }
    if (j == 0) g_last[b] = bidx;
}

// ---------------------------------------------------------------------------
// Main kernel: 192 CTAs x 128 threads (4 warps = 4 batches per CTA).
// ---------------------------------------------------------------------------
__global__ __launch_bounds__(128)
void crf_main_kernel(const float* __restrict__ pred,
                     const int*   __restrict__ amask,
                     const int*   __restrict__ labels,
                     const float* __restrict__ startv,
                     const float* __restrict__ endv,
                     const float* __restrict__ trans)
{
    const int role = blockIdx.x >> 6;
    const int wib  = threadIdx.x >> 5;
    const int b    = ((blockIdx.x & 63) << 2) | wib;
    const int j    = threadIdx.x & 31;

    const float* em = pred + (size_t)b * Sn * Tn;

    __shared__ __align__(16) float buf[4][2][32];
    __shared__ __align__(16) float ring[4][16][32];
    __shared__ signed char mkS[4][Sn];

    if (role == 2) {
        // ------- Numerator --------------------------------------------------
        const int* lab = labels + (size_t)b * Sn;
        const int* am  = amask  + (size_t)b * Sn;
        float sum = 0.f;
        int   msum = 0;
        for (int t = j; t < Sn; t += 32) {
            const int mt = am[t];
            msum += mt;
            const int tg = lab[t];
            if (t == 0) {
                sum += startv[tg] + em[tg];
            } else {
                const int tp = lab[t - 1];
                sum += (trans[tp * Tn + tg] + em[(size_t)t * Tn + tg]) * (float)mt;
            }
        }
        #pragma unroll
        for (int off = 16; off; off >>= 1) {
            sum  += __shfl_xor_sync(FULLMASK, sum, off);
            msum += __shfl_xor_sync(FULLMASK, msum, off);
        }
        if (j == 0) {
            const int se = msum - 1;
            const int lt = lab[se];
            g_num[b] = sum + endv[lt];
        }
        return;
    }

    // Load mask, detect all-ones (fast path valid for any input)
    const int* am = amask + (size_t)b * Sn;
    int okv = 1;
    for (int t = j; t < Sn; t += 32) {
        const int mv = am[t];
        mkS[wib][t] = (signed char)mv;
        okv &= (mv == 1);
    }
    const bool allones = __all_sync(FULLMASK, okv != 0);
    __syncwarp();

    float* bufw  = &buf[wib][0][0];
    float* ringw = &ring[wib][0][0];
    if (role == 0) {
        if (allones) fwd_loop<true >(em, j, bufw, ringw, mkS[wib], startv, endv, trans, b);
        else         fwd_loop<false>(em, j, bufw, ringw, mkS[wib], startv, endv, trans, b);
    } else {
        if (allones) vit_loop<true >(em, j, bufw, ringw, mkS[wib], startv, endv, trans, b);
        else         vit_loop<false>(em, j, bufw, ringw, mkS[wib], startv, endv, trans, b);
    }
}

// ---------------------------------------------------------------------------
// Backtrace phase 1: per (batch, chunk) warp computes the chunk's tag map
// (entry tag at top -> exit tag at bottom) for all 32 entry tags in parallel.
// ---------------------------------------------------------------------------
__global__ __launch_bounds__(128)
void bt_phase1(void)
{
    const int wib  = threadIdx.x >> 5;
    const int lane = threadIdx.x & 31;
    const int gw = (blockIdx.x << 2) | wib;       // 0 .. Bn*NCH-1
    const int b = gw >> 6;
    const int c = gw & 63;
    const int lo = c * 32;
    int hi = lo + 31; if (hi > Sn - 2) hi = Sn - 2;
    const int n = hi - lo + 1;

    __shared__ __align__(16) unsigned char sm[4][32 * Tn];
    unsigned char* S = sm[wib];
    const uint32_t* src = (const uint32_t*)(g_hist + ((size_t)b * (Sn - 1) + lo) * Tn);
    uint32_t* dst = (uint32_t*)S;
    for (int i = lane; i < n * 8; i += 32) dst[i] = src[i];
    __syncwarp();

    int tag = lane;
    for (int k = n - 1; k >= 0; --k) tag = S[k * Tn + tag];
    g_map[b][c][lane] = (unsigned char)tag;
}

// ---------------------------------------------------------------------------
// Backtrace phase 2: per batch, compose the 64 chunk maps from the top to get
// each chunk's entry tag. Also writes out[b][Sn-1].
// ---------------------------------------------------------------------------
__global__ __launch_bounds__(128)
void bt_phase2(float* __restrict__ out)
{
    const int wib  = threadIdx.x >> 5;
    const int lane = threadIdx.x & 31;
    const int b = (blockIdx.x << 2) | wib;

    __shared__ __align__(16) unsigned char sm[4][NCH * Tn];
    __shared__ unsigned char se[4][NCH];
    unsigned char* S = sm[wib];
    const uint32_t* src = (const uint32_t*)&g_map[b][0][0];
    uint32_t* dst = (uint32_t*)S;
    for (int i = lane; i < NCH * Tn / 4; i += 32) dst[i] = src[i];
    __syncwarp();

    if (lane == 0) {
        int e = g_last[b];
        out[(size_t)b * Sn + (Sn - 1)] = (float)e;
        for (int c = NCH - 1; c >= 0; --c) {
            se[wib][c] = (unsigned char)e;   // entry tag for chunk c
            e = S[c * Tn + e];               // exit = map[entry]
        }
    }
    __syncwarp();
    for (int c = lane; c < NCH; c += 32) g_ent[b][c] = se[wib][c];
}

// ---------------------------------------------------------------------------
// Backtrace phase 3: per (batch, chunk) warp re-chases its chunk from the
// known entry tag and writes the decoded tags (coalesced float stores).
// ---------------------------------------------------------------------------
__global__ __launch_bounds__(128)
void bt_phase3(float* __restrict__ out)
{
    const int wib  = threadIdx.x >> 5;
    const int lane = threadIdx.x & 31;
    const int gw = (blockIdx.x << 2) | wib;
    const int b = gw >> 6;
    const int c = gw & 63;
    const int lo = c * 32;
    int hi = lo + 31; if (hi > Sn - 2) hi = Sn - 2;
    const int n = hi - lo + 1;

    __shared__ __align__(16) unsigned char sm[4][32 * Tn];
    __shared__ unsigned char stag[4][32];
    unsigned char* S = sm[wib];
    const uint32_t* src = (const uint32_t*)(g_hist + ((size_t)b * (Sn - 1) + lo) * Tn);
    uint32_t* dst = (uint32_t*)S;
    for (int i = lane; i < n * 8; i += 32) dst[i] = src[i];
    __syncwarp();

    if (lane == 0) {
        int tag = g_ent[b][c];
        for (int k = n - 1; k >= 0; --k) {
            tag = S[k * Tn + tag];
            stag[wib][k] = (unsigned char)tag;
        }
    }
    __syncwarp();
    if (lane < n) out[(size_t)b * Sn + lo + lane] = (float)stag[wib][lane];
}

// ---------------------------------------------------------------------------
// Loss: -mean(num - den)
// ---------------------------------------------------------------------------
__global__ void crf_loss_kernel(float* __restrict__ out)
{
    __shared__ float red[Bn];
    const int t = threadIdx.x;
    red[t] = g_num[t] - g_den[t];
    __syncthreads();
    #pragma unroll
    for (int off = 128; off; off >>= 1) {
        if (t < off) red[t] += red[t + off];
        __syncthreads();
    }
    if (t == 0) out[(size_t)Bn * Sn] = -(red[0] / (float)Bn);
}

extern "C" void kernel_launch(void* const* d_in, const int* in_sizes, int n_in,
                              void* d_out, int out_size)
{
    const float* pred   = (const float*)d_in[0];
    const int*   amask  = (const int*)  d_in[1];
    const int*   labels = (const int*)  d_in[2];
    const float* startv = (const float*)d_in[3];
    const float* endv   = (const float*)d_in[4];
    const float* trans  = (const float*)d_in[5];
    float* out = (float*)d_out;

    crf_main_kernel<<<192, 128>>>(pred, amask, labels, startv, endv, trans);
    bt_phase1<<<(Bn * NCH) / 4, 128>>>();
    bt_phase2<<<Bn / 4, 128>>>(out);
    bt_phase3<<<(Bn * NCH) / 4, 128>>>(out);
    crf_loss_kernel<<<1, Bn>>>(out);
}